// round 2
// baseline (speedup 1.0000x reference)
#include <cuda_runtime.h>
#include <math.h>

// ---------------- problem constants ----------------
#define BB 256
#define NN 4096
#define DD 64
#define KK 16
#define ITERS 3
#define EPS_W 1e-8f
#define LN_EPS 1e-5f
#define SCALE 0.125f   // D^-0.5

// ---------------- scratch (device globals; no allocation allowed) ----------------
__device__ float g_k[(size_t)BB * NN * DD];      // 256 MB
__device__ float g_v[(size_t)BB * NN * DD];      // 256 MB
__device__ float g_slots[BB * KK * DD];
__device__ float g_q[BB * KK * DD];
__device__ float g_U[BB * KK * DD];
__device__ float g_S[BB * KK];

// ---------------- slot init: slots = mu + exp(0.5*logvar)*noise ----------------
__global__ void k_init_slots(const float* __restrict__ mu, const float* __restrict__ lv,
                             const float* __restrict__ noise) {
    int i = blockIdx.x * blockDim.x + threadIdx.x;
    if (i < BB * KK * DD) {
        int e = i & 63;
        g_slots[i] = mu[e] + expf(0.5f * lv[e]) * noise[i];
    }
}

// ---------------- fused LN(inputs) -> k,v projections ----------------
// One thread per (b,n) row. Weights transposed in shared: wT[d][j].
__global__ __launch_bounds__(128) void k_lnkv(
    const float* __restrict__ x,
    const float* __restrict__ wk, const float* __restrict__ bk,
    const float* __restrict__ wv, const float* __restrict__ bv,
    const float* __restrict__ gin, const float* __restrict__ bin)
{
    __shared__ float s_wkT[64 * 64];
    __shared__ float s_wvT[64 * 64];
    __shared__ float s_bk[64], s_bv[64], s_g[64], s_b[64];
    int tid = threadIdx.x;
    for (int i = tid; i < 4096; i += 128) {
        int j = i >> 6, d = i & 63;
        s_wkT[d * 64 + j] = wk[i];
        s_wvT[d * 64 + j] = wv[i];
    }
    if (tid < 64) { s_bk[tid] = bk[tid]; s_bv[tid] = bv[tid]; s_g[tid] = gin[tid]; s_b[tid] = bin[tid]; }
    __syncthreads();

    size_t row = (size_t)blockIdx.x * 128 + tid;            // b*N + n
    const float4* xr4 = (const float4*)(x + row * 64);

    // pass A: LN stats
    float m = 0.f;
    #pragma unroll
    for (int c = 0; c < 16; c++) {
        float4 t = xr4[c];
        m += t.x + t.y + t.z + t.w;
    }
    m *= (1.f / 64.f);
    float var = 0.f;
    #pragma unroll
    for (int c = 0; c < 16; c++) {
        float4 t = xr4[c];
        float a = t.x - m, b2 = t.y - m, c2 = t.z - m, d2 = t.w - m;
        var += a * a + b2 * b2 + c2 * c2 + d2 * d2;
    }
    var *= (1.f / 64.f);
    float rstd = rsqrtf(var + LN_EPS);

    // pass B: accumulate all 64 k-outs and 64 v-outs in registers
    float4 acck[16], accv[16];
    #pragma unroll
    for (int jj = 0; jj < 16; jj++) {
        acck[jj] = *(const float4*)&s_bk[jj * 4];
        accv[jj] = *(const float4*)&s_bv[jj * 4];
    }
    for (int c = 0; c < 16; c++) {
        float4 x4 = xr4[c];
        float4 g4 = *(const float4*)&s_g[c * 4];
        float4 b4 = *(const float4*)&s_b[c * 4];
        float xn[4];
        xn[0] = (x4.x - m) * rstd * g4.x + b4.x;
        xn[1] = (x4.y - m) * rstd * g4.y + b4.y;
        xn[2] = (x4.z - m) * rstd * g4.z + b4.z;
        xn[3] = (x4.w - m) * rstd * g4.w + b4.w;
        #pragma unroll
        for (int i = 0; i < 4; i++) {
            float xd = xn[i];
            int d = c * 4 + i;
            const float4* wk4 = (const float4*)&s_wkT[d * 64];
            const float4* wv4 = (const float4*)&s_wvT[d * 64];
            #pragma unroll
            for (int jj = 0; jj < 16; jj++) {
                float4 w = wk4[jj];
                acck[jj].x = fmaf(xd, w.x, acck[jj].x);
                acck[jj].y = fmaf(xd, w.y, acck[jj].y);
                acck[jj].z = fmaf(xd, w.z, acck[jj].z);
                acck[jj].w = fmaf(xd, w.w, acck[jj].w);
                float4 w2 = wv4[jj];
                accv[jj].x = fmaf(xd, w2.x, accv[jj].x);
                accv[jj].y = fmaf(xd, w2.y, accv[jj].y);
                accv[jj].z = fmaf(xd, w2.z, accv[jj].z);
                accv[jj].w = fmaf(xd, w2.w, accv[jj].w);
            }
        }
    }
    float4* ok = (float4*)(g_k + row * 64);
    float4* ov = (float4*)(g_v + row * 64);
    #pragma unroll
    for (int jj = 0; jj < 16; jj++) { ok[jj] = acck[jj]; ov[jj] = accv[jj]; }
}

// ---------------- q = LN(slots)@wq.T + bq ; also zeroes U,S for the iteration ----------------
__global__ __launch_bounds__(256) void k_qproj(
    const float* __restrict__ wq, const float* __restrict__ bq,
    const float* __restrict__ gsl, const float* __restrict__ bsl)
{
    __shared__ float s_row[4][64];
    __shared__ float s_ln[4][64];
    __shared__ float s_stat[4][2];
    int tid = threadIdx.x, r = tid >> 6, e = tid & 63;
    int row = blockIdx.x * 4 + r;                  // b*K + k
    s_row[r][e] = g_slots[row * 64 + e];
    g_U[row * 64 + e] = 0.f;
    __syncthreads();
    if (e == 0) {
        float m = 0.f;
        for (int d = 0; d < 64; d++) m += s_row[r][d];
        m *= (1.f / 64.f);
        float v = 0.f;
        for (int d = 0; d < 64; d++) { float t = s_row[r][d] - m; v += t * t; }
        v *= (1.f / 64.f);
        s_stat[r][0] = m; s_stat[r][1] = rsqrtf(v + LN_EPS);
        g_S[row] = 0.f;
    }
    __syncthreads();
    float m = s_stat[r][0], rs = s_stat[r][1];
    s_ln[r][e] = (s_row[r][e] - m) * rs * gsl[e] + bsl[e];
    __syncthreads();
    float acc = bq[e];
    const float4* wrow = (const float4*)(wq + e * 64);
    #pragma unroll
    for (int c = 0; c < 16; c++) {
        float4 w = wrow[c];
        float4 l = *(const float4*)&s_ln[r][c * 4];
        acc = fmaf(l.x, w.x, acc); acc = fmaf(l.y, w.y, acc);
        acc = fmaf(l.z, w.z, acc); acc = fmaf(l.w, w.w, acc);
    }
    g_q[row * 64 + e] = acc;
}

// ---------------- attend: logits -> softmax(over slots) -> accumulate S,U (or emit attn) ----------------
// grid (8, B): 8 chunks of 512 n per batch, 2 passes of 256 per chunk.
template <bool FINAL>
__global__ __launch_bounds__(256) void k_attend(float* __restrict__ out_attn)
{
    __shared__ float s_q[16 * 64];
    __shared__ float s_p[16 * 260];   // padded to avoid phase-2 bank conflicts
    __shared__ float s_S[16];
    int tid = threadIdx.x;
    int b = blockIdx.y, chunk = blockIdx.x;
    for (int i = tid; i < 1024; i += 256) s_q[i] = g_q[b * 1024 + i];
    if (!FINAL && tid < 16) s_S[tid] = 0.f;
    float Sl[16];
    #pragma unroll
    for (int s = 0; s < 16; s++) Sl[s] = 0.f;
    float4 uacc = make_float4(0.f, 0.f, 0.f, 0.f);
    int ks = tid & 15, dg = tid >> 4;
    __syncthreads();

    #pragma unroll
    for (int pass = 0; pass < 2; pass++) {
        int nbase = chunk * 512 + pass * 256;
        int n = nbase + tid;
        const float4* krow = (const float4*)(g_k + ((size_t)b * NN + n) * 64);
        float l[16];
        #pragma unroll
        for (int s = 0; s < 16; s++) l[s] = 0.f;
        for (int c = 0; c < 16; c++) {
            float4 kk = krow[c];
            #pragma unroll
            for (int s = 0; s < 16; s++) {
                float4 q = *(const float4*)&s_q[s * 64 + 4 * c];
                l[s] = fmaf(kk.x, q.x, l[s]);
                l[s] = fmaf(kk.y, q.y, l[s]);
                l[s] = fmaf(kk.z, q.z, l[s]);
                l[s] = fmaf(kk.w, q.w, l[s]);
            }
        }
        float mx = -1e30f;
        #pragma unroll
        for (int s = 0; s < 16; s++) { l[s] *= SCALE; mx = fmaxf(mx, l[s]); }
        float sum = 0.f;
        #pragma unroll
        for (int s = 0; s < 16; s++) { l[s] = __expf(l[s] - mx); sum += l[s]; }
        float inv = 1.f / sum;

        if (FINAL) {
            #pragma unroll
            for (int s = 0; s < 16; s++)
                out_attn[((size_t)(b * 16 + s)) * NN + n] = l[s] * inv;
        } else {
            #pragma unroll
            for (int s = 0; s < 16; s++) {
                float p = l[s] * inv + EPS_W;
                Sl[s] += p;
                s_p[s * 260 + tid] = p;
            }
            __syncthreads();
            const float* vbase = g_v + ((size_t)b * NN + nbase) * 64;
            for (int j = 0; j < 256; j += 4) {
                float4 p4 = *(const float4*)&s_p[ks * 260 + j];
                const float* v0 = vbase + (size_t)j * 64 + dg * 4;
                float4 a = *(const float4*)(v0);
                float4 b2 = *(const float4*)(v0 + 64);
                float4 c2 = *(const float4*)(v0 + 128);
                float4 d2 = *(const float4*)(v0 + 192);
                uacc.x = fmaf(p4.x, a.x, uacc.x); uacc.x = fmaf(p4.y, b2.x, uacc.x);
                uacc.x = fmaf(p4.z, c2.x, uacc.x); uacc.x = fmaf(p4.w, d2.x, uacc.x);
                uacc.y = fmaf(p4.x, a.y, uacc.y); uacc.y = fmaf(p4.y, b2.y, uacc.y);
                uacc.y = fmaf(p4.z, c2.y, uacc.y); uacc.y = fmaf(p4.w, d2.y, uacc.y);
                uacc.z = fmaf(p4.x, a.z, uacc.z); uacc.z = fmaf(p4.y, b2.z, uacc.z);
                uacc.z = fmaf(p4.z, c2.z, uacc.z); uacc.z = fmaf(p4.w, d2.z, uacc.z);
                uacc.w = fmaf(p4.x, a.w, uacc.w); uacc.w = fmaf(p4.y, b2.w, uacc.w);
                uacc.w = fmaf(p4.z, c2.w, uacc.w); uacc.w = fmaf(p4.w, d2.w, uacc.w);
            }
            __syncthreads();
        }
    }

    if (!FINAL) {
        #pragma unroll
        for (int s = 0; s < 16; s++) atomicAdd(&s_S[s], Sl[s]);
        float* Ub = g_U + (size_t)(b * 16 + ks) * 64 + dg * 4;
        atomicAdd(&Ub[0], uacc.x);
        atomicAdd(&Ub[1], uacc.y);
        atomicAdd(&Ub[2], uacc.z);
        atomicAdd(&Ub[3], uacc.w);
        __syncthreads();
        if (tid < 16) atomicAdd(&g_S[b * 16 + tid], s_S[tid]);
    }
}

// ---------------- GRU cell + LN + MLP residual, per (b,k) row ----------------
__global__ __launch_bounds__(256) void k_gru_mlp(
    const float* __restrict__ w_ih, const float* __restrict__ w_hh,
    const float* __restrict__ b_ih, const float* __restrict__ b_hh,
    const float* __restrict__ gml, const float* __restrict__ bml,
    const float* __restrict__ w1, const float* __restrict__ b1,
    const float* __restrict__ w2, const float* __restrict__ b2)
{
    __shared__ float s_upd[4][64], s_prev[4][64], s_new[4][64], s_ln[4][64], s_h1[4][128];
    __shared__ float s_stat[4][2];
    int tid = threadIdx.x, r = tid >> 6, e = tid & 63;
    int row = blockIdx.x * 4 + r;
    float Sv = g_S[row];
    s_upd[r][e] = g_U[row * 64 + e] / Sv;
    s_prev[r][e] = g_slots[row * 64 + e];
    __syncthreads();

    float xr = b_ih[e], xz = b_ih[64 + e], xn = b_ih[128 + e];
    float hr = b_hh[e], hz = b_hh[64 + e], hn = b_hh[128 + e];
    const float4* wir = (const float4*)(w_ih + (size_t)e * 64);
    const float4* wiz = (const float4*)(w_ih + (size_t)(64 + e) * 64);
    const float4* win = (const float4*)(w_ih + (size_t)(128 + e) * 64);
    const float4* whr = (const float4*)(w_hh + (size_t)e * 64);
    const float4* whz = (const float4*)(w_hh + (size_t)(64 + e) * 64);
    const float4* whn = (const float4*)(w_hh + (size_t)(128 + e) * 64);
    #pragma unroll
    for (int c = 0; c < 16; c++) {
        float4 u = *(const float4*)&s_upd[r][c * 4];
        float4 p = *(const float4*)&s_prev[r][c * 4];
        float4 w;
        w = wir[c]; xr = fmaf(u.x, w.x, xr); xr = fmaf(u.y, w.y, xr); xr = fmaf(u.z, w.z, xr); xr = fmaf(u.w, w.w, xr);
        w = wiz[c]; xz = fmaf(u.x, w.x, xz); xz = fmaf(u.y, w.y, xz); xz = fmaf(u.z, w.z, xz); xz = fmaf(u.w, w.w, xz);
        w = win[c]; xn = fmaf(u.x, w.x, xn); xn = fmaf(u.y, w.y, xn); xn = fmaf(u.z, w.z, xn); xn = fmaf(u.w, w.w, xn);
        w = whr[c]; hr = fmaf(p.x, w.x, hr); hr = fmaf(p.y, w.y, hr); hr = fmaf(p.z, w.z, hr); hr = fmaf(p.w, w.w, hr);
        w = whz[c]; hz = fmaf(p.x, w.x, hz); hz = fmaf(p.y, w.y, hz); hz = fmaf(p.z, w.z, hz); hz = fmaf(p.w, w.w, hz);
        w = whn[c]; hn = fmaf(p.x, w.x, hn); hn = fmaf(p.y, w.y, hn); hn = fmaf(p.z, w.z, hn); hn = fmaf(p.w, w.w, hn);
    }
    float rg = 1.f / (1.f + expf(-(xr + hr)));
    float zg = 1.f / (1.f + expf(-(xz + hz)));
    float ng = tanhf(xn + rg * hn);
    float sn = (1.f - zg) * ng + zg * s_prev[r][e];
    s_new[r][e] = sn;
    __syncthreads();
    if (e == 0) {
        float m = 0.f;
        for (int d = 0; d < 64; d++) m += s_new[r][d];
        m *= (1.f / 64.f);
        float v = 0.f;
        for (int d = 0; d < 64; d++) { float t = s_new[r][d] - m; v += t * t; }
        v *= (1.f / 64.f);
        s_stat[r][0] = m; s_stat[r][1] = rsqrtf(v + LN_EPS);
    }
    __syncthreads();
    float m = s_stat[r][0], rs = s_stat[r][1];
    s_ln[r][e] = (sn - m) * rs * gml[e] + bml[e];
    __syncthreads();
    #pragma unroll
    for (int t = 0; t < 2; t++) {
        int h = e + 64 * t;
        float a = b1[h];
        const float4* w1r = (const float4*)(w1 + (size_t)h * 64);
        #pragma unroll
        for (int c = 0; c < 16; c++) {
            float4 lv = *(const float4*)&s_ln[r][c * 4];
            float4 w = w1r[c];
            a = fmaf(lv.x, w.x, a); a = fmaf(lv.y, w.y, a);
            a = fmaf(lv.z, w.z, a); a = fmaf(lv.w, w.w, a);
        }
        s_h1[r][h] = fmaxf(a, 0.f);
    }
    __syncthreads();
    float o = b2[e];
    const float4* w2r = (const float4*)(w2 + (size_t)e * 128);
    #pragma unroll
    for (int c = 0; c < 32; c++) {
        float4 h = *(const float4*)&s_h1[r][c * 4];
        float4 w = w2r[c];
        o = fmaf(h.x, w.x, o); o = fmaf(h.y, w.y, o);
        o = fmaf(h.z, w.z, o); o = fmaf(h.w, w.w, o);
    }
    g_slots[row * 64 + e] = sn + o;
}

__global__ void k_copy_slots(float* __restrict__ out) {
    int i = blockIdx.x * blockDim.x + threadIdx.x;
    if (i < BB * KK * DD) out[i] = g_slots[i];
}

// ---------------- launch ----------------
extern "C" void kernel_launch(void* const* d_in, const int* in_sizes, int n_in,
                              void* d_out, int out_size) {
    const float* inputs = (const float*)d_in[0];
    // d_in[1] = mask: all-true, and constant-over-slots => no-op for slot-axis softmax. Ignored.
    const float* noise = (const float*)d_in[2];
    const float* mu    = (const float*)d_in[3];
    const float* lv    = (const float*)d_in[4];
    const float* wq = (const float*)d_in[5];  const float* bq = (const float*)d_in[6];
    const float* wk = (const float*)d_in[7];  const float* bk = (const float*)d_in[8];
    const float* wv = (const float*)d_in[9];  const float* bv = (const float*)d_in[10];
    const float* w_ih = (const float*)d_in[11]; const float* w_hh = (const float*)d_in[12];
    const float* b_ih = (const float*)d_in[13]; const float* b_hh = (const float*)d_in[14];
    const float* gin = (const float*)d_in[15]; const float* bin = (const float*)d_in[16];
    const float* gsl = (const float*)d_in[17]; const float* bsl = (const float*)d_in[18];
    const float* gml = (const float*)d_in[19]; const float* bml = (const float*)d_in[20];
    const float* w1 = (const float*)d_in[21]; const float* b1 = (const float*)d_in[22];
    const float* w2 = (const float*)d_in[23]; const float* b2 = (const float*)d_in[24];

    float* out = (float*)d_out;
    const int SZ_SLOTS = BB * KK * DD;
    const int SZ_ATTN  = BB * KK * NN;
    float* out_slots = nullptr;
    float* out_attn  = nullptr;
    if (out_size >= SZ_SLOTS + SZ_ATTN) { out_slots = out; out_attn = out + SZ_SLOTS; }
    else if (out_size >= SZ_ATTN)       { out_attn = out; }
    else                                { out_slots = out; }

    k_init_slots<<<(BB * KK * DD + 255) / 256, 256>>>(mu, lv, noise);
    k_lnkv<<<BB * NN / 128, 128>>>(inputs, wk, bk, wv, bv, gin, bin);

    for (int it = 0; it < ITERS; it++) {
        k_qproj<<<BB * KK / 4, 256>>>(wq, bq, gsl, bsl);
        k_attend<false><<<dim3(8, BB), 256>>>(nullptr);
        k_gru_mlp<<<BB * KK / 4, 256>>>(w_ih, w_hh, b_ih, b_hh, gml, bml, w1, b1, w2, b2);
    }
    k_qproj<<<BB * KK / 4, 256>>>(wq, bq, gsl, bsl);
    // If attn isn't part of the output, dump it into g_v (dead after the loop).
    float* attn_dst = out_attn ? out_attn : g_v;
    k_attend<true><<<dim3(8, BB), 256>>>(attn_dst);
    if (out_slots) k_copy_slots<<<(BB * KK * DD + 255) / 256, 256>>>(out_slots);
}